// round 7
// baseline (speedup 1.0000x reference)
#include <cuda_runtime.h>
#include <cuda_fp16.h>
#include <math.h>
#include <stdint.h>

#define D_TOT 2304
#define OUTC  512
#define INC   256
#define HWX   3136          // 56*56
#define NIMG  16
#define NPIX  (NIMG*HWX)    // 50176

#define BK    32
#define NITER (D_TOT/BK)    // 72
#define MT    256           // CTA M tile (channels)
#define NT    128           // CTA N tile (pixels)
#define NTHR  512

// B SMEM (u32 units): fragment-ordered packed-half2, double buffered.
#define B_NSTRIDE 66
#define B_KSTRIDE 1056      // 16*66
#define B_BUF     2112      // 2*1056

// A SMEM: fragment-ordered stream, 4096 u32 per stage, 3 stages (cp.async).
#define A_STAGE_U32 4096
#define SMEM_BYTES  (3*A_STAGE_U32*4 + 2*B_BUF*4)   // 66048

// scratch (device globals: no allocation allowed)
__device__ int   g_kidx[OUTC];
__device__ float g_maxrow[D_TOT];
__device__ float g_mul[OUTC];
__device__ int   g_sel[OUTC];
__device__ int   g_active;
// A fragment stream: [mt(2)][iter(72)][4096 u32]  = 2.36 MB (L2-resident)
__device__ __align__(16) uint32_t g_Wa[2 * NITER * A_STAGE_U32];

// ============================ PTX helpers ====================================
__device__ __forceinline__ uint32_t smem_u32(const void* p) {
    uint32_t a;
    asm("{ .reg .u64 t; cvta.to.shared.u64 t, %1; cvt.u32.u64 %0, t; }"
        : "=r"(a) : "l"(p));
    return a;
}
__device__ __forceinline__ void cp16(uint32_t dst, const void* src) {
    asm volatile("cp.async.cg.shared.global [%0], [%1], 16;"
                 :: "r"(dst), "l"(src) : "memory");
}
#define CP_COMMIT() asm volatile("cp.async.commit_group;" ::: "memory")
#define CP_WAIT(n)  asm volatile("cp.async.wait_group %0;" :: "n"(n) : "memory")

__device__ __forceinline__ uint32_t packh2(float lo, float hi) {
    __half2 h = __floats2half2_rn(lo, hi);
    return *reinterpret_cast<uint32_t*>(&h);
}
__device__ __forceinline__ void mma16(float* c, const uint32_t* a, const uint32_t* b) {
    asm volatile(
        "mma.sync.aligned.m16n8k16.row.col.f32.f16.f16.f32 "
        "{%0,%1,%2,%3}, {%4,%5,%6,%7}, {%8,%9}, {%0,%1,%2,%3};\n"
        : "+f"(c[0]), "+f"(c[1]), "+f"(c[2]), "+f"(c[3])
        : "r"(a[0]), "r"(a[1]), "r"(a[2]), "r"(a[3]), "r"(b[0]), "r"(b[1]));
}

// ============================ small kernels ==================================
__global__ void __launch_bounds__(256) hash_kernels(const float* __restrict__ W,
                                                    const float* __restrict__ a) {
    const int o   = blockIdx.x;
    const int tid = threadIdx.x;
    const float* w = W + (size_t)o * D_TOT;
    float dot = 0.f, n2 = 0.f;
    for (int i = tid; i < D_TOT; i += 256) {
        float v = w[i];
        dot += a[i] * v;
        n2  += v * v;
    }
    __shared__ float s1[256], s2[256];
    s1[tid] = dot; s2[tid] = n2;
    __syncthreads();
    for (int st = 128; st > 0; st >>= 1) {
        if (tid < st) { s1[tid] += s1[tid+st]; s2[tid] += s2[tid+st]; }
        __syncthreads();
    }
    if (tid == 0) {
        float acc = s1[0];
        float pw  = s2[0];
        acc += a[D_TOT+0] * pw; pw *= pw;
        acc += a[D_TOT+1] * pw; pw *= pw;
        acc += a[D_TOT+2] * pw; pw *= pw;
        acc += a[D_TOT+3] * pw; pw *= pw;
        acc += a[D_TOT+4] * pw;
        float h = floorf(acc);
        float r = fmodf(h, 16.f);
        if (r < 0.f) r += 16.f;
        g_kidx[o] = (int)r;
    }
}

__global__ void __launch_bounds__(256) max_rows(const float* __restrict__ x) {
    const int c   = blockIdx.x;
    const int tid = threadIdx.x;
    float m[9];
#pragma unroll
    for (int i = 0; i < 9; i++) m[i] = -1e30f;
    for (int t = tid; t < NIMG * HWX; t += 256) {
        int n = t / HWX;
        int i = t - n * HWX;
        int r = i / 56;
        int s = i - r * 56;
        float v = __ldg(&x[((size_t)n * INC + c) * HWX + i]);
        bool r0 = (r <= 54), r2 = (r >= 1), c0 = (s <= 54), c2 = (s >= 1);
        m[4] = fmaxf(m[4], v);
        if (r0) { m[1] = fmaxf(m[1], v); if (c0) m[0] = fmaxf(m[0], v); if (c2) m[2] = fmaxf(m[2], v); }
        if (c0) m[3] = fmaxf(m[3], v);
        if (c2) m[5] = fmaxf(m[5], v);
        if (r2) { m[7] = fmaxf(m[7], v); if (c0) m[6] = fmaxf(m[6], v); if (c2) m[8] = fmaxf(m[8], v); }
    }
    __shared__ float sred[256];
    for (int q = 0; q < 9; q++) {
        sred[tid] = m[q];
        __syncthreads();
        for (int st = 128; st > 0; st >>= 1) {
            if (tid < st) sred[tid] = fmaxf(sred[tid], sred[tid+st]);
            __syncthreads();
        }
        if (tid == 0) {
            float mv = sred[0];
            if (q != 4) mv = fmaxf(mv, 0.f);
            g_maxrow[q * INC + c] = mv;
        }
        __syncthreads();
    }
}

__global__ void __launch_bounds__(512) build_route(const float* __restrict__ a) {
    const int tid = threadIdx.x;
    __shared__ float red[512];

    float ss = 0.f;
    for (int i = tid; i < D_TOT; i += 512) { float v = g_maxrow[i]; ss += v * v; }
    red[tid] = ss; __syncthreads();
    for (int st = 256; st > 0; st >>= 1) { if (tid < st) red[tid] += red[tid+st]; __syncthreads(); }
    __shared__ float s_norm;
    if (tid == 0) s_norm = sqrtf(red[0]);
    __syncthreads();

    float dot = 0.f;
    for (int i = tid; i < D_TOT; i += 512) dot += a[i] * g_maxrow[i];
    red[tid] = dot; __syncthreads();
    for (int st = 256; st > 0; st >>= 1) { if (tid < st) red[tid] += red[tid+st]; __syncthreads(); }

    __shared__ int s_q, s_cnt, s_pos;
    if (tid == 0) {
        float hs = 0.5f * (a[D_TOT] + a[D_TOT+1] + a[D_TOT+2] + a[D_TOT+3] + a[D_TOT+4]);
        float acc = red[0] / s_norm + hs;
        float h = floorf(acc);
        float r = fmodf(h, 16.f);
        if (r < 0.f) r += 16.f;
        s_q = (int)r;
        s_cnt = 0; s_pos = 0;
    }
    __syncthreads();

    int match = (g_kidx[tid] == s_q) ? 1 : 0;
    if (match) atomicAdd(&s_cnt, 1);
    __syncthreads();
    int count = s_cnt;

    if (count > 0) {
        g_mul[tid] = match ? ((float)OUTC / (float)count) : 0.f;
        if (match) { int pp = atomicAdd(&s_pos, 1); g_sel[pp] = tid; }
        if (tid == 0) g_active = count;
    } else {
        g_mul[tid] = 1.f;
        g_sel[tid] = tid;
        if (tid == 0) g_active = OUTC;
    }
}

__global__ void __launch_bounds__(256) fill_bias(float4* __restrict__ out,
                                                 const float* __restrict__ bias) {
    if (g_active == OUTC) return;   // conv writes every channel in this case
    int i = blockIdx.x * 256 + threadIdx.x;
#pragma unroll
    for (int t = 0; t < 16; t++) {
        int o = (i / 784) & 511;
        float b = __ldg(&bias[o]);
        out[i] = make_float4(b, b, b, b);
        i += 1568 * 256;
    }
}

// Build A fragment stream for MT=256: stage layout [kstep(2)][mtile(16)][lane(32)][reg(4)]
// Must run AFTER build_route (uses g_sel / g_active).
__global__ void __launch_bounds__(256) w2frag(const float* __restrict__ W) {
    const int mt  = blockIdx.x;      // 0..1
    const int it  = blockIdx.y;      // 0..71
    const int tid = threadIdx.x;
    const int active = g_active;
    uint32_t v[16];
#pragma unroll
    for (int j = 0; j < 16; j++) {
        int s     = tid * 16 + j;
        int kstep = s >> 11;
        int mtile = (s >> 7) & 15;
        int lane  = (s >> 2) & 31;
        int reg   = s & 3;
        int m  = mtile * 16 + (lane >> 2) + (reg & 1) * 8;
        int kl = kstep * 16 + (lane & 3) * 2 + ((reg >> 1) & 1) * 8;
        int k  = it * 32 + kl;
        int gi = mt * MT + m;
        int g  = (gi < active) ? g_sel[gi] : 0;
        float2 w2 = __ldg((const float2*)&W[(size_t)g * D_TOT + k]);
        v[j] = packh2(w2.x, w2.y);
    }
    uint32_t* dst = g_Wa + ((size_t)(mt * NITER + it)) * A_STAGE_U32 + tid * 16;
#pragma unroll
    for (int q4 = 0; q4 < 4; q4++)
        *(uint4*)(dst + q4 * 4) = make_uint4(v[q4*4], v[q4*4+1], v[q4*4+2], v[q4*4+3]);
}

// ============================ tensor-core conv ===============================
// D[m,n] = sum_k A[m,k]*B[n,k]; A from g_Wa fragment stream via cp.async,
// B built on the fly from L2-resident x. MT=256, 512 threads, 16 warps.
__global__ void __launch_bounds__(NTHR, 1) conv_mma(const float* __restrict__ x,
                                                    const float* __restrict__ bias,
                                                    float* __restrict__ out) {
    const int active = g_active;
    const int mt = blockIdx.x;
    if (mt * MT >= active) return;
    const int nt  = blockIdx.y;
    const int tid = threadIdx.x;
    const int wid  = tid >> 5;
    const int lane = tid & 31;
    const int wm = wid & 3;             // 0..3 (64 rows each)
    const int wn = wid >> 2;            // 0..3 (32 cols each)

    extern __shared__ __align__(16) uint32_t smem[];
    uint32_t* smA = smem;                       // 3 * 4096 u32
    uint32_t* smB = smem + 3 * A_STAGE_U32;     // 2 * 2112 u32

    const uint32_t sA = smem_u32(smA);
    const uint32_t* aSrc = g_Wa + (size_t)mt * NITER * A_STAGE_U32;
    const uint32_t aDstOff = (uint32_t)tid * 32;   // bytes (512 thr x 32B = 16KB)

    // ---- B staging: thread (np, kq): pixel np, k-eighth kq (8 k = 4 pairs) ----
    const int np = tid & 127;
    const int kq = tid >> 7;            // 0..3
    const int p  = nt * NT + np;
    const int pn = p / HWX;
    const int prem = p - pn * HWX;
    const int py = prem / 56;
    const int px = prem - py * 56;
    const float* xb = x + (size_t)pn * INC * HWX;
    const int b_base = (kq >> 1) * B_KSTRIDE + (np >> 3) * B_NSTRIDE
                     + (np & 7) * 8 + (kq & 1);

    uint32_t bP[4];

    // ---------------- prologue ----------------
#pragma unroll
    for (int s = 0; s < 2; s++) {
        const uint32_t d = sA + (uint32_t)s * (A_STAGE_U32 * 4) + aDstOff;
        const uint32_t* src = aSrc + s * A_STAGE_U32 + tid * 8;
        cp16(d, src);
        cp16(d + 16, src + 4);
        CP_COMMIT();
    }
    {   // B chunk 0 -> buf 0 (tap (0,0))
        const int r = py - 1, s = px - 1;
        const bool ok = ((unsigned)r < 56u) && ((unsigned)s < 56u);
        const float* bp = xb + (size_t)(kq * 8) * HWX + r * 56 + s;
#pragma unroll
        for (int j = 0; j < 4; j++) {
            float v0 = ok ? __ldg(bp + (2*j) * HWX)   : 0.f;
            float v1 = ok ? __ldg(bp + (2*j+1) * HWX) : 0.f;
            bP[j] = packh2(v0, v1);
        }
#pragma unroll
        for (int j = 0; j < 4; j++) smB[b_base + j * 2] = bP[j];
    }

    float acc[4][4][4];
#pragma unroll
    for (int i = 0; i < 4; i++)
#pragma unroll
        for (int j = 0; j < 4; j++)
#pragma unroll
            for (int r = 0; r < 4; r++) acc[i][j][r] = 0.f;

#pragma unroll 1
    for (int it = 0; it < NITER; it++) {
        // ---- prefetch next B chunk to regs ----
        if (it + 1 < NITER) {
            const int k0 = (it + 1) * BK;
            const int t9 = k0 >> 8;
            const int khh = (t9 * 11) >> 5;     // t9/3
            const int kww = t9 - 3 * khh;
            const int r  = py + khh - 1;
            const int s  = px + kww - 1;
            const bool ok = ((unsigned)r < 56u) && ((unsigned)s < 56u);
            const float* bp = xb + (size_t)((k0 & 255) + kq * 8) * HWX + r * 56 + s;
#pragma unroll
            for (int j = 0; j < 4; j++) {
                float v0 = ok ? __ldg(bp + (2*j) * HWX)   : 0.f;
                float v1 = ok ? __ldg(bp + (2*j+1) * HWX) : 0.f;
                bP[j] = packh2(v0, v1);
            }
        }

        // ---- own A(it) copies done, then make everything visible ----
        if (it + 1 < NITER) CP_WAIT(1); else CP_WAIT(0);
        __syncthreads();

        // ---- issue A(it+2) into the stage freed by iter it-1 ----
        if (it + 2 < NITER) {
            const int st = (it + 2) % 3;
            const uint32_t d = sA + (uint32_t)st * (A_STAGE_U32 * 4) + aDstOff;
            const uint32_t* src = aSrc + (it + 2) * A_STAGE_U32 + tid * 8;
            cp16(d, src);
            cp16(d + 16, src + 4);
            CP_COMMIT();
        }

        // ---- compute ----
        const uint32_t aoff = (uint32_t)(it % 3) * A_STAGE_U32;
        const uint32_t boff = (uint32_t)(it & 1) * B_BUF;
#pragma unroll
        for (int ks = 0; ks < 2; ks++) {
            uint32_t af[4][4], bf[4][2];
#pragma unroll
            for (int j = 0; j < 4; j++) {
                uint4 v = *(const uint4*)&smA[aoff + ks * 2048
                                              + (wm * 4 + j) * 128 + lane * 4];
                af[j][0] = v.x; af[j][1] = v.y; af[j][2] = v.z; af[j][3] = v.w;
            }
#pragma unroll
            for (int j = 0; j < 4; j++) {
                uint2 v = *(const uint2*)&smB[boff + ks * B_KSTRIDE
                                              + (wn * 4 + j) * B_NSTRIDE + lane * 2];
                bf[j][0] = v.x; bf[j][1] = v.y;
            }
#pragma unroll
            for (int mi = 0; mi < 4; mi++)
#pragma unroll
                for (int nj = 0; nj < 4; nj++)
                    mma16(acc[mi][nj], af[mi], bf[nj]);
        }

        // ---- store next B chunk into other buffer ----
        if (it + 1 < NITER) {
            const uint32_t nb = (uint32_t)((it + 1) & 1) * B_BUF;
#pragma unroll
            for (int j = 0; j < 4; j++)
                smB[nb + b_base + j * 2] = bP[j];
        }
    }

    // ---------------- epilogue ----------------
#pragma unroll
    for (int mi = 0; mi < 4; mi++) {
        const int row0 = wm * 64 + mi * 16 + (lane >> 2);
#pragma unroll
        for (int rp = 0; rp < 2; rp++) {
            const int m  = row0 + rp * 8;
            const int gi = mt * MT + m;
            if (gi >= active) continue;
            const int g  = g_sel[gi];
            const float mu = g_mul[g];
            const float bb = __ldg(&bias[g]);
#pragma unroll
            for (int nj = 0; nj < 4; nj++) {
                const int col = wn * 32 + nj * 8 + 2 * (lane & 3);
                const int pp  = nt * NT + col;
                const int n   = pp / HWX;
                const int rem = pp - n * HWX;
                float2 v;
                v.x = fmaf(mu, acc[mi][nj][rp * 2 + 0], bb);
                v.y = fmaf(mu, acc[mi][nj][rp * 2 + 1], bb);
                *(float2*)&out[((size_t)n * OUTC + g) * HWX + rem] = v;
            }
        }
    }
}

// ============================================================================
extern "C" void kernel_launch(void* const* d_in, const int* in_sizes, int n_in,
                              void* d_out, int out_size) {
    const float* x = nullptr;
    const float* W = nullptr;
    const float* bias = nullptr;
    const float* a = nullptr;
    for (int i = 0; i < n_in; i++) {
        if (in_sizes[i] == NIMG * INC * HWX)      x    = (const float*)d_in[i];
        else if (in_sizes[i] == OUTC * D_TOT)     W    = (const float*)d_in[i];
        else if (in_sizes[i] == OUTC)             bias = (const float*)d_in[i];
        else if (in_sizes[i] == D_TOT + 5)        a    = (const float*)d_in[i];
    }
    float* out = (float*)d_out;

    cudaFuncSetAttribute(conv_mma, cudaFuncAttributeMaxDynamicSharedMemorySize,
                         SMEM_BYTES);

    hash_kernels<<<OUTC, 256>>>(W, a);
    max_rows<<<INC, 256>>>(x);
    build_route<<<1, 512>>>(a);
    w2frag<<<dim3(2, NITER), 256>>>(W);
    fill_bias<<<1568, 256>>>((float4*)out, bias);
    conv_mma<<<dim3(2, NPIX / NT), NTHR, SMEM_BYTES>>>(x, bias, out);
}

// round 8
// speedup vs baseline: 1.0445x; 1.0445x over previous
#include <cuda_runtime.h>
#include <cuda_fp16.h>
#include <math.h>
#include <stdint.h>

#define D_TOT 2304
#define OUTC  512
#define INC   256
#define HWX   3136          // 56*56
#define NIMG  16
#define NPIX  (NIMG*HWX)    // 50176

#define BK    32
#define NITER (D_TOT/BK)    // 72
#define MT    128           // CTA M tile (channels)
#define NT    128           // CTA N tile (pixels)

// Unified 3-stage cp.async ring.
// Stage: A frag stream 2048 u32 (8KB) + B tile 2*128*12 u32 (12KB) = 5120 u32.
#define A_STAGE_U32 2048
#define B_SLOT_U32  12                  // 8 used + 4 pad (48B, 16B-aligned)
#define STAGE_U32   (A_STAGE_U32 + 2*128*B_SLOT_U32)   // 5120
#define STAGE_BYTES (STAGE_U32*4)                      // 20480
#define SMEM_BYTES  (3*STAGE_BYTES)                    // 61440

// scratch (device globals: no allocation allowed)
__device__ int   g_kidx[OUTC];
__device__ float g_maxrow[D_TOT];
__device__ float g_mul[OUTC];
__device__ int   g_sel[OUTC];
__device__ int   g_active;
// A fragment stream: [mt(4)][iter(72)][2048 u32] = 2.36 MB (L2-resident)
__device__ __align__(16) uint32_t g_Wa[4 * NITER * A_STAGE_U32];
// x in NHWC half: [pixel(50176)][c(256)] = 25.7 MB (L2-resident)
__device__ __align__(16) __half g_xh[(size_t)NPIX * INC];

// ============================ PTX helpers ====================================
__device__ __forceinline__ uint32_t smem_u32(const void* p) {
    uint32_t a;
    asm("{ .reg .u64 t; cvta.to.shared.u64 t, %1; cvt.u32.u64 %0, t; }"
        : "=r"(a) : "l"(p));
    return a;
}
__device__ __forceinline__ void cp16(uint32_t dst, const void* src) {
    asm volatile("cp.async.cg.shared.global [%0], [%1], 16;"
                 :: "r"(dst), "l"(src) : "memory");
}
// zero-fill variant: src-size 0 -> fill 16B with zeros
__device__ __forceinline__ void cp16z(uint32_t dst, const void* src, uint32_t sz) {
    asm volatile("cp.async.cg.shared.global [%0], [%1], 16, %2;"
                 :: "r"(dst), "l"(src), "r"(sz) : "memory");
}
#define CP_COMMIT() asm volatile("cp.async.commit_group;" ::: "memory")
#define CP_WAIT(n)  asm volatile("cp.async.wait_group %0;" :: "n"(n) : "memory")

__device__ __forceinline__ uint32_t packh2(float lo, float hi) {
    __half2 h = __floats2half2_rn(lo, hi);
    return *reinterpret_cast<uint32_t*>(&h);
}
__device__ __forceinline__ void mma16(float* c, const uint32_t* a, const uint32_t* b) {
    asm volatile(
        "mma.sync.aligned.m16n8k16.row.col.f32.f16.f16.f32 "
        "{%0,%1,%2,%3}, {%4,%5,%6,%7}, {%8,%9}, {%0,%1,%2,%3};\n"
        : "+f"(c[0]), "+f"(c[1]), "+f"(c[2]), "+f"(c[3])
        : "r"(a[0]), "r"(a[1]), "r"(a[2]), "r"(a[3]), "r"(b[0]), "r"(b[1]));
}

// ============================ small kernels ==================================
__global__ void __launch_bounds__(256) hash_kernels(const float* __restrict__ W,
                                                    const float* __restrict__ a) {
    const int o   = blockIdx.x;
    const int tid = threadIdx.x;
    const float* w = W + (size_t)o * D_TOT;
    float dot = 0.f, n2 = 0.f;
    for (int i = tid; i < D_TOT; i += 256) {
        float v = w[i];
        dot += a[i] * v;
        n2  += v * v;
    }
    __shared__ float s1[256], s2[256];
    s1[tid] = dot; s2[tid] = n2;
    __syncthreads();
    for (int st = 128; st > 0; st >>= 1) {
        if (tid < st) { s1[tid] += s1[tid+st]; s2[tid] += s2[tid+st]; }
        __syncthreads();
    }
    if (tid == 0) {
        float acc = s1[0];
        float pw  = s2[0];
        acc += a[D_TOT+0] * pw; pw *= pw;
        acc += a[D_TOT+1] * pw; pw *= pw;
        acc += a[D_TOT+2] * pw; pw *= pw;
        acc += a[D_TOT+3] * pw; pw *= pw;
        acc += a[D_TOT+4] * pw;
        float h = floorf(acc);
        float r = fmodf(h, 16.f);
        if (r < 0.f) r += 16.f;
        g_kidx[o] = (int)r;
    }
}

__global__ void __launch_bounds__(256) max_rows(const float* __restrict__ x) {
    const int c   = blockIdx.x;
    const int tid = threadIdx.x;
    float m[9];
#pragma unroll
    for (int i = 0; i < 9; i++) m[i] = -1e30f;
    for (int t = tid; t < NIMG * HWX; t += 256) {
        int n = t / HWX;
        int i = t - n * HWX;
        int r = i / 56;
        int s = i - r * 56;
        float v = __ldg(&x[((size_t)n * INC + c) * HWX + i]);
        bool r0 = (r <= 54), r2 = (r >= 1), c0 = (s <= 54), c2 = (s >= 1);
        m[4] = fmaxf(m[4], v);
        if (r0) { m[1] = fmaxf(m[1], v); if (c0) m[0] = fmaxf(m[0], v); if (c2) m[2] = fmaxf(m[2], v); }
        if (c0) m[3] = fmaxf(m[3], v);
        if (c2) m[5] = fmaxf(m[5], v);
        if (r2) { m[7] = fmaxf(m[7], v); if (c0) m[6] = fmaxf(m[6], v); if (c2) m[8] = fmaxf(m[8], v); }
    }
    __shared__ float sred[256];
    for (int q = 0; q < 9; q++) {
        sred[tid] = m[q];
        __syncthreads();
        for (int st = 128; st > 0; st >>= 1) {
            if (tid < st) sred[tid] = fmaxf(sred[tid], sred[tid+st]);
            __syncthreads();
        }
        if (tid == 0) {
            float mv = sred[0];
            if (q != 4) mv = fmaxf(mv, 0.f);
            g_maxrow[q * INC + c] = mv;
        }
        __syncthreads();
    }
}

__global__ void __launch_bounds__(512) build_route(const float* __restrict__ a) {
    const int tid = threadIdx.x;
    __shared__ float red[512];

    float ss = 0.f;
    for (int i = tid; i < D_TOT; i += 512) { float v = g_maxrow[i]; ss += v * v; }
    red[tid] = ss; __syncthreads();
    for (int st = 256; st > 0; st >>= 1) { if (tid < st) red[tid] += red[tid+st]; __syncthreads(); }
    __shared__ float s_norm;
    if (tid == 0) s_norm = sqrtf(red[0]);
    __syncthreads();

    float dot = 0.f;
    for (int i = tid; i < D_TOT; i += 512) dot += a[i] * g_maxrow[i];
    red[tid] = dot; __syncthreads();
    for (int st = 256; st > 0; st >>= 1) { if (tid < st) red[tid] += red[tid+st]; __syncthreads(); }

    __shared__ int s_q, s_cnt, s_pos;
    if (tid == 0) {
        float hs = 0.5f * (a[D_TOT] + a[D_TOT+1] + a[D_TOT+2] + a[D_TOT+3] + a[D_TOT+4]);
        float acc = red[0] / s_norm + hs;
        float h = floorf(acc);
        float r = fmodf(h, 16.f);
        if (r < 0.f) r += 16.f;
        s_q = (int)r;
        s_cnt = 0; s_pos = 0;
    }
    __syncthreads();

    int match = (g_kidx[tid] == s_q) ? 1 : 0;
    if (match) atomicAdd(&s_cnt, 1);
    __syncthreads();
    int count = s_cnt;

    if (count > 0) {
        g_mul[tid] = match ? ((float)OUTC / (float)count) : 0.f;
        if (match) { int pp = atomicAdd(&s_pos, 1); g_sel[pp] = tid; }
        if (tid == 0) g_active = count;
    } else {
        g_mul[tid] = 1.f;
        g_sel[tid] = tid;
        if (tid == 0) g_active = OUTC;
    }
}

__global__ void __launch_bounds__(256) fill_bias(float4* __restrict__ out,
                                                 const float* __restrict__ bias) {
    if (g_active == OUTC) return;   // conv writes every channel in this case
    int i = blockIdx.x * 256 + threadIdx.x;
#pragma unroll
    for (int t = 0; t < 16; t++) {
        int o = (i / 784) & 511;
        float b = __ldg(&bias[o]);
        out[i] = make_float4(b, b, b, b);
        i += 1568 * 256;
    }
}

// Build A fragment stream (round-6 layout, MT=128).
__global__ void __launch_bounds__(256) w2frag(const float* __restrict__ W) {
    const int mt  = blockIdx.x;      // 0..3
    const int it  = blockIdx.y;      // 0..71
    const int tid = threadIdx.x;
    const int active = g_active;
    uint32_t v[8];
#pragma unroll
    for (int j = 0; j < 8; j++) {
        int s     = tid * 8 + j;
        int kstep = s >> 10;
        int mtile = (s >> 7) & 7;
        int lane  = (s >> 2) & 31;
        int reg   = s & 3;
        int m  = mtile * 16 + (lane >> 2) + (reg & 1) * 8;
        int kl = kstep * 16 + (lane & 3) * 2 + ((reg >> 1) & 1) * 8;
        int k  = it * 32 + kl;
        int gi = mt * MT + m;
        int g  = (gi < active) ? g_sel[gi] : 0;
        float2 w2 = __ldg((const float2*)&W[(size_t)g * D_TOT + k]);
        v[j] = packh2(w2.x, w2.y);
    }
    uint32_t* dst = g_Wa + ((size_t)(mt * NITER + it)) * A_STAGE_U32 + tid * 8;
    *(uint4*)dst       = make_uint4(v[0], v[1], v[2], v[3]);
    *(uint4*)(dst + 4) = make_uint4(v[4], v[5], v[6], v[7]);
}

// x NCHW f32 -> g_xh NHWC half. SMEM-tiled transpose, coalesced both sides.
__global__ void __launch_bounds__(256) x2nhwc(const float* __restrict__ x) {
    __shared__ float sx[32][129];
    const int tid = threadIdx.x;
    const int c0  = blockIdx.y * 32;
    const int pg0 = blockIdx.x * 128;
#pragma unroll
    for (int e = 0; e < 16; e++) {
        int idx = tid + e * 256;
        int c_l = idx >> 7;
        int p_l = idx & 127;
        int pg  = pg0 + p_l;
        int n   = pg / HWX;
        int pi  = pg - n * HWX;
        sx[c_l][p_l] = __ldg(&x[((size_t)n * INC + c0 + c_l) * HWX + pi]);
    }
    __syncthreads();
#pragma unroll
    for (int e = 0; e < 2; e++) {
        int q = tid + e * 256;          // 0..511
        int p_l = q >> 2;
        int cg  = q & 3;
        uint32_t u[4];
#pragma unroll
        for (int j = 0; j < 4; j++)
            u[j] = packh2(sx[cg * 8 + 2*j][p_l], sx[cg * 8 + 2*j + 1][p_l]);
        *(uint4*)&g_xh[(size_t)(pg0 + p_l) * INC + c0 + cg * 8]
            = make_uint4(u[0], u[1], u[2], u[3]);
    }
}

// ============================ tensor-core conv ===============================
// D[m,n] = sum_k A[m,k]*B[n,k]; A from g_Wa, B from g_xh (NHWC half),
// both via unified 3-stage cp.async ring. MT=128, 256 thr, 2 CTAs/SM.
__global__ void __launch_bounds__(256, 2) conv_mma(const float* __restrict__ bias,
                                                   float* __restrict__ out) {
    const int active = g_active;
    const int mt = blockIdx.x;
    if (mt * MT >= active) return;
    const int nt  = blockIdx.y;
    const int tid = threadIdx.x;
    const int wid  = tid >> 5;
    const int lane = tid & 31;
    const int wm = wid & 1;             // 0..1 (64 rows)
    const int wn = wid >> 1;            // 0..3 (32 cols)

    extern __shared__ __align__(16) uint32_t smem[];
    const uint32_t sbase = smem_u32(smem);

    const uint32_t* aSrc = g_Wa + (size_t)mt * NITER * A_STAGE_U32;
    const uint32_t aDstOff = (uint32_t)tid * 32;   // bytes

    // B staging role: (np, khq): pixel np, kstep khq, 16 contiguous channels.
    const int np  = tid & 127;
    const int khq = tid >> 7;           // 0/1
    const int p   = nt * NT + np;
    const int pn  = p / HWX;
    const int prem = p - pn * HWX;
    const int py  = prem / 56;
    const int px  = prem - py * 56;
    const uint32_t bDstOff = 8192u + (uint32_t)(khq * 128 + np) * 48u;

    float acc[4][4][4];
#pragma unroll
    for (int i = 0; i < 4; i++)
#pragma unroll
        for (int j = 0; j < 4; j++)
#pragma unroll
            for (int r = 0; r < 4; r++) acc[i][j][r] = 0.f;

    // ---- stage issue (A + B, one commit) ----
#define ISSUE_STAGE(IT) do {                                                   \
        const int _it = (IT);                                                  \
        const uint32_t _sb = sbase + (uint32_t)(_it % 3) * STAGE_BYTES;        \
        const uint32_t* _sa = aSrc + _it * A_STAGE_U32 + tid * 8;              \
        cp16(_sb + aDstOff,      _sa);                                         \
        cp16(_sb + aDstOff + 16, _sa + 4);                                     \
        const int _k0 = _it * BK;                                              \
        const int _t9 = _k0 >> 8;                                              \
        const int _kh = (_t9 * 11) >> 5;                                       \
        const int _kw = _t9 - 3 * _kh;                                         \
        const int _r  = py + _kh - 1;                                          \
        const int _s  = px + _kw - 1;                                          \
        const bool _ok = ((unsigned)_r < 56u) && ((unsigned)_s < 56u);         \
        const __half* _sbp = _ok ?                                             \
            (g_xh + ((size_t)(pn * HWX + _r * 56 + _s)) * INC                  \
                  + (_k0 & 255) + khq * 16) : g_xh;                            \
        const uint32_t _sz = _ok ? 16u : 0u;                                   \
        cp16z(_sb + bDstOff,      _sbp,     _sz);                              \
        cp16z(_sb + bDstOff + 16, _sbp + 8, _sz);                              \
        CP_COMMIT();                                                           \
    } while (0)

    ISSUE_STAGE(0);
    ISSUE_STAGE(1);

#pragma unroll 1
    for (int it = 0; it < NITER; it++) {
        if (it + 1 < NITER) CP_WAIT(1); else CP_WAIT(0);
        __syncthreads();

        if (it + 2 < NITER) ISSUE_STAGE(it + 2);

        const uint32_t st = (uint32_t)(it % 3) * STAGE_U32;
#pragma unroll
        for (int ks = 0; ks < 2; ks++) {
            uint32_t af[4][4], bf[4][2];
#pragma unroll
            for (int j = 0; j < 4; j++) {
                uint4 v = *(const uint4*)&smem[st + ks * 1024
                                               + (wm * 4 + j) * 128 + lane * 4];
                af[j][0] = v.x; af[j][1] = v.y; af[j][2] = v.z; af[j][3] = v.w;
            }
#pragma unroll
            for (int nj = 0; nj < 4; nj++) {
                const uint32_t bi = st + 2048
                    + (uint32_t)(ks * 128 + wn * 32 + nj * 8 + (lane >> 2)) * 12u
                    + (lane & 3);
                bf[nj][0] = smem[bi];
                bf[nj][1] = smem[bi + 4];
            }
#pragma unroll
            for (int mi = 0; mi < 4; mi++)
#pragma unroll
                for (int nj = 0; nj < 4; nj++)
                    mma16(acc[mi][nj], af[mi], bf[nj]);
        }
    }

    // ---------------- epilogue ----------------
#pragma unroll
    for (int mi = 0; mi < 4; mi++) {
        const int row0 = wm * 64 + mi * 16 + (lane >> 2);
#pragma unroll
        for (int rp = 0; rp < 2; rp++) {
            const int m  = row0 + rp * 8;
            const int gi = mt * MT + m;
            if (gi >= active) continue;
            const int g  = g_sel[gi];
            const float mu = g_mul[g];
            const float bb = __ldg(&bias[g]);
#pragma unroll
            for (int nj = 0; nj < 4; nj++) {
                const int col = wn * 32 + nj * 8 + 2 * (lane & 3);
                const int pp  = nt * NT + col;
                const int n   = pp / HWX;
                const int rem = pp - n * HWX;
                float2 v;
                v.x = fmaf(mu, acc[mi][nj][rp * 2 + 0], bb);
                v.y = fmaf(mu, acc[mi][nj][rp * 2 + 1], bb);
                *(float2*)&out[((size_t)n * OUTC + g) * HWX + rem] = v;
            }
        }
    }
}

// ============================================================================
extern "C" void kernel_launch(void* const* d_in, const int* in_sizes, int n_in,
                              void* d_out, int out_size) {
    const float* x = nullptr;
    const float* W = nullptr;
    const float* bias = nullptr;
    const float* a = nullptr;
    for (int i = 0; i < n_in; i++) {
        if (in_sizes[i] == NIMG * INC * HWX)      x    = (const float*)d_in[i];
        else if (in_sizes[i] == OUTC * D_TOT)     W    = (const float*)d_in[i];
        else if (in_sizes[i] == OUTC)             bias = (const float*)d_in[i];
        else if (in_sizes[i] == D_TOT + 5)        a    = (const float*)d_in[i];
    }
    float* out = (float*)d_out;

    cudaFuncSetAttribute(conv_mma, cudaFuncAttributeMaxDynamicSharedMemorySize,
                         SMEM_BYTES);

    hash_kernels<<<OUTC, 256>>>(W, a);
    max_rows<<<INC, 256>>>(x);
    build_route<<<1, 512>>>(a);
    w2frag<<<dim3(4, NITER), 256>>>(W);
    x2nhwc<<<dim3(NPIX / 128, INC / 32), 256>>>(x);
    fill_bias<<<1568, 256>>>((float4*)out, bias);
    conv_mma<<<dim3(4, NPIX / NT), 256, SMEM_BYTES>>>(bias, out);
}

// round 9
// speedup vs baseline: 1.1794x; 1.1291x over previous
#include <cuda_runtime.h>
#include <cuda_fp16.h>
#include <math.h>
#include <stdint.h>

#define D_TOT 2304
#define OUTC  512
#define INC   256
#define HWX   3136          // 56*56
#define NIMG  16
#define NPIX  (NIMG*HWX)    // 50176

#define BK    32
#define NITER (D_TOT/BK)    // 72
#define MT    128           // CTA M tile (channels)
#define NT    128           // CTA N tile (pixels)

// Unified 3-stage cp.async ring.
// Stage: A frag stream 2048 u32 (8KB) + B 128 pixels x 20 u32 (10KB).
#define A_STAGE_U32 2048
#define B_PIX_U32   20      // 16 used + 4 pad (conflict-free banks)
#define STAGE_U32   (A_STAGE_U32 + 128*B_PIX_U32)   // 4608
#define STAGE_BYTES (STAGE_U32*4)                   // 18432
#define SMEM_BYTES  (3*STAGE_BYTES)                 // 55296

// scratch (device globals: no allocation allowed)
__device__ int   g_kidx[OUTC];
__device__ float g_maxrow[D_TOT];
__device__ float g_mul[OUTC];
__device__ int   g_sel[OUTC];
__device__ int   g_active;
// A fragment stream: [mt(4)][iter(72)][2048 u32] = 2.36 MB (L2-resident)
__device__ __align__(16) uint32_t g_Wa[4 * NITER * A_STAGE_U32];
// x tiled half: [cchunk(8)][pixel(50176)][32 ch] = 25.7 MB (L2-resident)
__device__ __align__(16) __half g_xt[(size_t)8 * NPIX * 32];

// ============================ PTX helpers ====================================
__device__ __forceinline__ uint32_t smem_u32(const void* p) {
    uint32_t a;
    asm("{ .reg .u64 t; cvta.to.shared.u64 t, %1; cvt.u32.u64 %0, t; }"
        : "=r"(a) : "l"(p));
    return a;
}
__device__ __forceinline__ void cp16(uint32_t dst, const void* src) {
    asm volatile("cp.async.cg.shared.global [%0], [%1], 16;"
                 :: "r"(dst), "l"(src) : "memory");
}
// zero-fill variant: src-size 0 -> fill 16B with zeros
__device__ __forceinline__ void cp16z(uint32_t dst, const void* src, uint32_t sz) {
    asm volatile("cp.async.cg.shared.global [%0], [%1], 16, %2;"
                 :: "r"(dst), "l"(src), "r"(sz) : "memory");
}
#define CP_COMMIT() asm volatile("cp.async.commit_group;" ::: "memory")
#define CP_WAIT(n)  asm volatile("cp.async.wait_group %0;" :: "n"(n) : "memory")

__device__ __forceinline__ uint32_t packh2(float lo, float hi) {
    __half2 h = __floats2half2_rn(lo, hi);
    return *reinterpret_cast<uint32_t*>(&h);
}
__device__ __forceinline__ void mma16(float* c, const uint32_t* a, const uint32_t* b) {
    asm volatile(
        "mma.sync.aligned.m16n8k16.row.col.f32.f16.f16.f32 "
        "{%0,%1,%2,%3}, {%4,%5,%6,%7}, {%8,%9}, {%0,%1,%2,%3};\n"
        : "+f"(c[0]), "+f"(c[1]), "+f"(c[2]), "+f"(c[3])
        : "r"(a[0]), "r"(a[1]), "r"(a[2]), "r"(a[3]), "r"(b[0]), "r"(b[1]));
}

// ============================ small kernels ==================================
__global__ void __launch_bounds__(256) hash_kernels(const float* __restrict__ W,
                                                    const float* __restrict__ a) {
    const int o   = blockIdx.x;
    const int tid = threadIdx.x;
    const float* w = W + (size_t)o * D_TOT;
    float dot = 0.f, n2 = 0.f;
    for (int i = tid; i < D_TOT; i += 256) {
        float v = w[i];
        dot += a[i] * v;
        n2  += v * v;
    }
    __shared__ float s1[256], s2[256];
    s1[tid] = dot; s2[tid] = n2;
    __syncthreads();
    for (int st = 128; st > 0; st >>= 1) {
        if (tid < st) { s1[tid] += s1[tid+st]; s2[tid] += s2[tid+st]; }
        __syncthreads();
    }
    if (tid == 0) {
        float acc = s1[0];
        float pw  = s2[0];
        acc += a[D_TOT+0] * pw; pw *= pw;
        acc += a[D_TOT+1] * pw; pw *= pw;
        acc += a[D_TOT+2] * pw; pw *= pw;
        acc += a[D_TOT+3] * pw; pw *= pw;
        acc += a[D_TOT+4] * pw;
        float h = floorf(acc);
        float r = fmodf(h, 16.f);
        if (r < 0.f) r += 16.f;
        g_kidx[o] = (int)r;
    }
}

__global__ void __launch_bounds__(256) max_rows(const float* __restrict__ x) {
    const int c   = blockIdx.x;
    const int tid = threadIdx.x;
    float m[9];
#pragma unroll
    for (int i = 0; i < 9; i++) m[i] = -1e30f;
    for (int t = tid; t < NIMG * HWX; t += 256) {
        int n = t / HWX;
        int i = t - n * HWX;
        int r = i / 56;
        int s = i - r * 56;
        float v = __ldg(&x[((size_t)n * INC + c) * HWX + i]);
        bool r0 = (r <= 54), r2 = (r >= 1), c0 = (s <= 54), c2 = (s >= 1);
        m[4] = fmaxf(m[4], v);
        if (r0) { m[1] = fmaxf(m[1], v); if (c0) m[0] = fmaxf(m[0], v); if (c2) m[2] = fmaxf(m[2], v); }
        if (c0) m[3] = fmaxf(m[3], v);
        if (c2) m[5] = fmaxf(m[5], v);
        if (r2) { m[7] = fmaxf(m[7], v); if (c0) m[6] = fmaxf(m[6], v); if (c2) m[8] = fmaxf(m[8], v); }
    }
    __shared__ float sred[256];
    for (int q = 0; q < 9; q++) {
        sred[tid] = m[q];
        __syncthreads();
        for (int st = 128; st > 0; st >>= 1) {
            if (tid < st) sred[tid] = fmaxf(sred[tid], sred[tid+st]);
            __syncthreads();
        }
        if (tid == 0) {
            float mv = sred[0];
            if (q != 4) mv = fmaxf(mv, 0.f);
            g_maxrow[q * INC + c] = mv;
        }
        __syncthreads();
    }
}

__global__ void __launch_bounds__(512) build_route(const float* __restrict__ a) {
    const int tid = threadIdx.x;
    __shared__ float red[512];

    float ss = 0.f;
    for (int i = tid; i < D_TOT; i += 512) { float v = g_maxrow[i]; ss += v * v; }
    red[tid] = ss; __syncthreads();
    for (int st = 256; st > 0; st >>= 1) { if (tid < st) red[tid] += red[tid+st]; __syncthreads(); }
    __shared__ float s_norm;
    if (tid == 0) s_norm = sqrtf(red[0]);
    __syncthreads();

    float dot = 0.f;
    for (int i = tid; i < D_TOT; i += 512) dot += a[i] * g_maxrow[i];
    red[tid] = dot; __syncthreads();
    for (int st = 256; st > 0; st >>= 1) { if (tid < st) red[tid] += red[tid+st]; __syncthreads(); }

    __shared__ int s_q, s_cnt, s_pos;
    if (tid == 0) {
        float hs = 0.5f * (a[D_TOT] + a[D_TOT+1] + a[D_TOT+2] + a[D_TOT+3] + a[D_TOT+4]);
        float acc = red[0] / s_norm + hs;
        float h = floorf(acc);
        float r = fmodf(h, 16.f);
        if (r < 0.f) r += 16.f;
        s_q = (int)r;
        s_cnt = 0; s_pos = 0;
    }
    __syncthreads();

    int match = (g_kidx[tid] == s_q) ? 1 : 0;
    if (match) atomicAdd(&s_cnt, 1);
    __syncthreads();
    int count = s_cnt;

    if (count > 0) {
        g_mul[tid] = match ? ((float)OUTC / (float)count) : 0.f;
        if (match) { int pp = atomicAdd(&s_pos, 1); g_sel[pp] = tid; }
        if (tid == 0) g_active = count;
    } else {
        g_mul[tid] = 1.f;
        g_sel[tid] = tid;
        if (tid == 0) g_active = OUTC;
    }
}

__global__ void __launch_bounds__(256) fill_bias(float4* __restrict__ out,
                                                 const float* __restrict__ bias) {
    if (g_active == OUTC) return;   // conv writes every channel in this case
    int i = blockIdx.x * 256 + threadIdx.x;
#pragma unroll
    for (int t = 0; t < 16; t++) {
        int o = (i / 784) & 511;
        float b = __ldg(&bias[o]);
        out[i] = make_float4(b, b, b, b);
        i += 1568 * 256;
    }
}

// Build A fragment stream (round-6 layout, MT=128).
__global__ void __launch_bounds__(256) w2frag(const float* __restrict__ W) {
    const int mt  = blockIdx.x;      // 0..3
    const int it  = blockIdx.y;      // 0..71
    const int tid = threadIdx.x;
    const int active = g_active;
    uint32_t v[8];
#pragma unroll
    for (int j = 0; j < 8; j++) {
        int s     = tid * 8 + j;
        int kstep = s >> 10;
        int mtile = (s >> 7) & 7;
        int lane  = (s >> 2) & 31;
        int reg   = s & 3;
        int m  = mtile * 16 + (lane >> 2) + (reg & 1) * 8;
        int kl = kstep * 16 + (lane & 3) * 2 + ((reg >> 1) & 1) * 8;
        int k  = it * 32 + kl;
        int gi = mt * MT + m;
        int g  = (gi < active) ? g_sel[gi] : 0;
        float2 w2 = __ldg((const float2*)&W[(size_t)g * D_TOT + k]);
        v[j] = packh2(w2.x, w2.y);
    }
    uint32_t* dst = g_Wa + ((size_t)(mt * NITER + it)) * A_STAGE_U32 + tid * 8;
    *(uint4*)dst       = make_uint4(v[0], v[1], v[2], v[3]);
    *(uint4*)(dst + 4) = make_uint4(v[4], v[5], v[6], v[7]);
}

// x NCHW f32 -> g_xt[cchunk][pixel][32ch] half. SMEM-tiled, coalesced both sides.
__global__ void __launch_bounds__(256) x2tile(const float* __restrict__ x) {
    __shared__ float sx[32][129];
    const int tid = threadIdx.x;
    const int kc  = blockIdx.y;         // channel chunk 0..7
    const int pg0 = blockIdx.x * 128;
#pragma unroll
    for (int e = 0; e < 16; e++) {
        int idx = tid + e * 256;
        int c_l = idx >> 7;
        int p_l = idx & 127;
        int pg  = pg0 + p_l;
        int n   = pg / HWX;
        int pi  = pg - n * HWX;
        sx[c_l][p_l] = __ldg(&x[((size_t)n * INC + kc * 32 + c_l) * HWX + pi]);
    }
    __syncthreads();
#pragma unroll
    for (int e = 0; e < 2; e++) {
        int q = tid + e * 256;          // 0..511
        int p_l = q >> 2;
        int cg  = q & 3;
        uint32_t u[4];
#pragma unroll
        for (int j = 0; j < 4; j++)
            u[j] = packh2(sx[cg * 8 + 2*j][p_l], sx[cg * 8 + 2*j + 1][p_l]);
        *(uint4*)&g_xt[((size_t)kc * NPIX + pg0 + p_l) * 32 + cg * 8]
            = make_uint4(u[0], u[1], u[2], u[3]);
    }
}

// ============================ tensor-core conv ===============================
// D[m,n] = sum_k A[m,k]*B[n,k]; A from g_Wa, B from g_xt (tiled half),
// both via unified 3-stage cp.async ring. k order identical to round 6:
// it -> tap = it>>3, cchunk = it&7, k0 = it*32.
__global__ void __launch_bounds__(256, 2) conv_mma(const float* __restrict__ bias,
                                                   float* __restrict__ out) {
    const int active = g_active;
    const int mt = blockIdx.x;
    if (mt * MT >= active) return;
    const int nt  = blockIdx.y;
    const int tid = threadIdx.x;
    const int wid  = tid >> 5;
    const int lane = tid & 31;
    const int wm = wid & 1;             // 0..1 (64 rows)
    const int wn = wid >> 1;            // 0..3 (32 cols)

    extern __shared__ __align__(16) uint32_t smem[];
    const uint32_t sbase = smem_u32(smem);

    const uint32_t* aSrc = g_Wa + (size_t)mt * NITER * A_STAGE_U32;
    const uint32_t aDstOff = (uint32_t)tid * 32;   // bytes

    // B staging role: thread -> pixel np = tid>>1, 16B slot-pair hs = tid&1.
    const int np = tid >> 1;
    const int hs = tid & 1;
    const int p  = nt * NT + np;
    const int pn = p / HWX;
    const int prem = p - pn * HWX;
    const int py = prem / 56;
    const int px = prem - py * 56;
    const uint32_t bDst = 8192u + (uint32_t)np * 80u + (uint32_t)hs * 32u;
    // base for this pixel's image at tap offset 0
    const __half* xtp = g_xt + ((size_t)pn * HWX + prem) * 32 + hs * 16;

    float acc[4][4][4];
#pragma unroll
    for (int i = 0; i < 4; i++)
#pragma unroll
        for (int j = 0; j < 4; j++)
#pragma unroll
            for (int r = 0; r < 4; r++) acc[i][j][r] = 0.f;

#define ISSUE_STAGE(IT) do {                                                   \
        const int _it = (IT);                                                  \
        const uint32_t _sb = sbase + (uint32_t)(_it % 3) * STAGE_BYTES;        \
        const uint32_t* _sa = aSrc + _it * A_STAGE_U32 + tid * 8;              \
        cp16(_sb + aDstOff,      _sa);                                         \
        cp16(_sb + aDstOff + 16, _sa + 4);                                     \
        const int _tap = _it >> 3;                                             \
        const int _kc  = _it & 7;                                              \
        const int _kh  = (_tap * 11) >> 5;                                     \
        const int _kw  = _tap - 3 * _kh;                                       \
        const int _r   = py + _kh - 1;                                         \
        const int _s   = px + _kw - 1;                                         \
        const bool _ok = ((unsigned)_r < 56u) && ((unsigned)_s < 56u);         \
        const long _off = (long)_kc * NPIX + ((_kh - 1) * 56 + (_kw - 1));     \
        const __half* _src = _ok ? (xtp + _off * 32) : (const __half*)g_xt;    \
        const uint32_t _sz = _ok ? 16u : 0u;                                   \
        cp16z(_sb + bDst,      _src,     _sz);                                 \
        cp16z(_sb + bDst + 16, _src + 8, _sz);                                 \
        CP_COMMIT();                                                           \
    } while (0)

    ISSUE_STAGE(0);
    ISSUE_STAGE(1);

#pragma unroll 1
    for (int it = 0; it < NITER; it++) {
        if (it + 1 < NITER) CP_WAIT(1); else CP_WAIT(0);
        __syncthreads();

        if (it + 2 < NITER) ISSUE_STAGE(it + 2);

        const uint32_t st = (uint32_t)(it % 3) * STAGE_U32;
#pragma unroll
        for (int ks = 0; ks < 2; ks++) {
            uint32_t af[4][4], bf[4][2];
#pragma unroll
            for (int j = 0; j < 4; j++) {
                uint4 v = *(const uint4*)&smem[st + ks * 1024
                                               + (wm * 4 + j) * 128 + lane * 4];
                af[j][0] = v.x; af[j][1] = v.y; af[j][2] = v.z; af[j][3] = v.w;
            }
#pragma unroll
            for (int nj = 0; nj < 4; nj++) {
                const uint32_t bi = st + 2048
                    + (uint32_t)(wn * 32 + nj * 8 + (lane >> 2)) * 20u
                    + (uint32_t)(ks * 8 + (lane & 3));
                bf[nj][0] = smem[bi];
                bf[nj][1] = smem[bi + 4];
            }
#pragma unroll
            for (int mi = 0; mi < 4; mi++)
#pragma unroll
                for (int nj = 0; nj < 4; nj++)
                    mma16(acc[mi][nj], af[mi], bf[nj]);
        }
    }

    // ---------------- epilogue ----------------
#pragma unroll
    for (int mi = 0; mi < 4; mi++) {
        const int row0 = wm * 64 + mi * 16 + (lane >> 2);
#pragma unroll
        for (int rp = 0; rp < 2; rp++) {
            const int m  = row0 + rp * 8;
            const int gi = mt * MT + m;
            if (gi >= active) continue;
            const int g  = g_sel[gi];
            const float mu = g_mul[g];
            const float bb = __ldg(&bias[g]);
#pragma unroll
            for (int nj = 0; nj < 4; nj++) {
                const int col = wn * 32 + nj * 8 + 2 * (lane & 3);
                const int pp  = nt * NT + col;
                const int n   = pp / HWX;
                const int rem = pp - n * HWX;
                float2 v;
                v.x = fmaf(mu, acc[mi][nj][rp * 2 + 0], bb);
                v.y = fmaf(mu, acc[mi][nj][rp * 2 + 1], bb);
                *(float2*)&out[((size_t)n * OUTC + g) * HWX + rem] = v;
            }
        }
    }
}

// ============================================================================
extern "C" void kernel_launch(void* const* d_in, const int* in_sizes, int n_in,
                              void* d_out, int out_size) {
    const float* x = nullptr;
    const float* W = nullptr;
    const float* bias = nullptr;
    const float* a = nullptr;
    for (int i = 0; i < n_in; i++) {
        if (in_sizes[i] == NIMG * INC * HWX)      x    = (const float*)d_in[i];
        else if (in_sizes[i] == OUTC * D_TOT)     W    = (const float*)d_in[i];
        else if (in_sizes[i] == OUTC)             bias = (const float*)d_in[i];
        else if (in_sizes[i] == D_TOT + 5)        a    = (const float*)d_in[i];
    }
    float* out = (float*)d_out;

    cudaFuncSetAttribute(conv_mma, cudaFuncAttributeMaxDynamicSharedMemorySize,
                         SMEM_BYTES);

    hash_kernels<<<OUTC, 256>>>(W, a);
    max_rows<<<INC, 256>>>(x);
    build_route<<<1, 512>>>(a);
    w2frag<<<dim3(4, NITER), 256>>>(W);
    x2tile<<<dim3(NPIX / 128, 8), 256>>>(x);
    fill_bias<<<1568, 256>>>((float4*)out, bias);
    conv_mma<<<dim3(4, NPIX / NT), 256, SMEM_BYTES>>>(bias, out);
}